// round 1
// baseline (speedup 1.0000x reference)
#include <cuda_runtime.h>
#include <cuda_bf16.h>

// Problem: GridSamplePScan  B=1, L=16, C=8, H=128, W=128
// out[t,c,h,w] = sum_{k<=t} bilinear(images[k,c], base(h,w) + cum[t]-cum[k])
// x-coordinate wrapped periodically (mod 2 in normalized coords), zeros padding taps.

#define L_ 16
#define C_ 8
#define H_ 128
#define W_ 128
#define HW_ (H_ * W_)

// NHWC-transposed images scratch: [L, H, W, C] floats = 8 MB
__device__ float g_imgT[L_ * H_ * W_ * C_];

// ---------------------------------------------------------------------------
// Kernel 1: transpose images [L,C,H,W] -> [L,H,W,C]
// ---------------------------------------------------------------------------
__global__ __launch_bounds__(256) void transpose_nhwc_kernel(const float* __restrict__ images) {
    int idx = blockIdx.x * blockDim.x + threadIdx.x;  // over L*H*W
    if (idx >= L_ * HW_) return;
    int k = idx >> 14;           // / (H*W)
    int hw = idx & (HW_ - 1);    // h*W + w

    const float* src = images + (size_t)k * C_ * HW_ + hw;
    float4 lo, hi;
    lo.x = src[0 * HW_];
    lo.y = src[1 * HW_];
    lo.z = src[2 * HW_];
    lo.w = src[3 * HW_];
    hi.x = src[4 * HW_];
    hi.y = src[5 * HW_];
    hi.z = src[6 * HW_];
    hi.w = src[7 * HW_];

    float4* dst = reinterpret_cast<float4*>(g_imgT + (size_t)idx * C_);
    dst[0] = lo;
    dst[1] = hi;
}

// ---------------------------------------------------------------------------
// Kernel 2: fused suffix-sum flow + bilinear gather + triangular accumulation
// One thread per (t, h, w); accumulates all 8 channels in registers.
// ---------------------------------------------------------------------------
__global__ __launch_bounds__(128) void pscan_sample_kernel(const float* __restrict__ flows,
                                                           float* __restrict__ out) {
    const int w = threadIdx.x;     // 0..127
    const int h = blockIdx.x;      // 0..127
    const int t = blockIdx.y;      // 0..15
    const int hw = h * W_ + w;

    // base grid (pixel centers, normalized, align_corners=False)
    const float bx = (2.0f * (float)w + 1.0f) * (1.0f / (float)W_) - 1.0f;
    const float by = (2.0f * (float)h + 1.0f) * (1.0f / (float)H_) - 1.0f;

    float4 acc_lo = make_float4(0.f, 0.f, 0.f, 0.f);
    float4 acc_hi = make_float4(0.f, 0.f, 0.f, 0.f);

    // rel(t,k) = cum[t]-cum[k], built as suffix sum going k = t..0:
    //   rel(t,t)=0 ; rel(t,k-1) = rel(t,k) + flow[k]
    float rx = 0.0f, ry = 0.0f;

    for (int k = t; k >= 0; --k) {
        // normalized grid coords
        float gx = bx + rx;
        float gy = by + ry;

        // periodic wrap in x: remainder(gx+1, 2) - 1  (Python-mod semantics)
        float m = fmodf(gx + 1.0f, 2.0f);
        if (m < 0.0f) m += 2.0f;
        gx = m - 1.0f;

        // to pixel coords
        float ix = (gx + 1.0f) * ((float)W_ * 0.5f) - 0.5f;
        float iy = (gy + 1.0f) * ((float)H_ * 0.5f) - 0.5f;

        float x0f = floorf(ix);
        float y0f = floorf(iy);
        float wx = ix - x0f;
        float wy = iy - y0f;

        int x0 = (int)x0f;
        int y0 = (int)y0f;
        int x1 = x0 + 1;
        int y1 = y0 + 1;

        // validity (zeros padding)
        float vx0 = (x0 >= 0 && x0 < W_) ? 1.0f : 0.0f;
        float vx1 = (x1 >= 0 && x1 < W_) ? 1.0f : 0.0f;
        float vy0 = (y0 >= 0 && y0 < H_) ? 1.0f : 0.0f;
        float vy1 = (y1 >= 0 && y1 < H_) ? 1.0f : 0.0f;

        // clamped indices for safe loads
        int cx0 = min(max(x0, 0), W_ - 1);
        int cx1 = min(max(x1, 0), W_ - 1);
        int cy0 = min(max(y0, 0), H_ - 1);
        int cy1 = min(max(y1, 0), H_ - 1);

        float w00 = (1.0f - wx) * (1.0f - wy) * vx0 * vy0;
        float w10 = wx * (1.0f - wy) * vx1 * vy0;
        float w01 = (1.0f - wx) * wy * vx0 * vy1;
        float w11 = wx * wy * vx1 * vy1;

        const float* imgk = g_imgT + (size_t)k * HW_ * C_;

        const float4* p00 = reinterpret_cast<const float4*>(imgk + (size_t)(cy0 * W_ + cx0) * C_);
        const float4* p10 = reinterpret_cast<const float4*>(imgk + (size_t)(cy0 * W_ + cx1) * C_);
        const float4* p01 = reinterpret_cast<const float4*>(imgk + (size_t)(cy1 * W_ + cx0) * C_);
        const float4* p11 = reinterpret_cast<const float4*>(imgk + (size_t)(cy1 * W_ + cx1) * C_);

        float4 a, b;

        a = p00[0]; b = p00[1];
        acc_lo.x = fmaf(w00, a.x, acc_lo.x);
        acc_lo.y = fmaf(w00, a.y, acc_lo.y);
        acc_lo.z = fmaf(w00, a.z, acc_lo.z);
        acc_lo.w = fmaf(w00, a.w, acc_lo.w);
        acc_hi.x = fmaf(w00, b.x, acc_hi.x);
        acc_hi.y = fmaf(w00, b.y, acc_hi.y);
        acc_hi.z = fmaf(w00, b.z, acc_hi.z);
        acc_hi.w = fmaf(w00, b.w, acc_hi.w);

        a = p10[0]; b = p10[1];
        acc_lo.x = fmaf(w10, a.x, acc_lo.x);
        acc_lo.y = fmaf(w10, a.y, acc_lo.y);
        acc_lo.z = fmaf(w10, a.z, acc_lo.z);
        acc_lo.w = fmaf(w10, a.w, acc_lo.w);
        acc_hi.x = fmaf(w10, b.x, acc_hi.x);
        acc_hi.y = fmaf(w10, b.y, acc_hi.y);
        acc_hi.z = fmaf(w10, b.z, acc_hi.z);
        acc_hi.w = fmaf(w10, b.w, acc_hi.w);

        a = p01[0]; b = p01[1];
        acc_lo.x = fmaf(w01, a.x, acc_lo.x);
        acc_lo.y = fmaf(w01, a.y, acc_lo.y);
        acc_lo.z = fmaf(w01, a.z, acc_lo.z);
        acc_lo.w = fmaf(w01, a.w, acc_lo.w);
        acc_hi.x = fmaf(w01, b.x, acc_hi.x);
        acc_hi.y = fmaf(w01, b.y, acc_hi.y);
        acc_hi.z = fmaf(w01, b.z, acc_hi.z);
        acc_hi.w = fmaf(w01, b.w, acc_hi.w);

        a = p11[0]; b = p11[1];
        acc_lo.x = fmaf(w11, a.x, acc_lo.x);
        acc_lo.y = fmaf(w11, a.y, acc_lo.y);
        acc_lo.z = fmaf(w11, a.z, acc_lo.z);
        acc_lo.w = fmaf(w11, a.w, acc_lo.w);
        acc_hi.x = fmaf(w11, b.x, acc_hi.x);
        acc_hi.y = fmaf(w11, b.y, acc_hi.y);
        acc_hi.z = fmaf(w11, b.z, acc_hi.z);
        acc_hi.w = fmaf(w11, b.w, acc_hi.w);

        // advance suffix sum: add flow[k] for the next (k-1) iteration
        if (k > 0) {
            rx += __ldg(flows + (size_t)(k * 2 + 0) * HW_ + hw);
            ry += __ldg(flows + (size_t)(k * 2 + 1) * HW_ + hw);
        }
    }

    // store: out[t, c, h, w]  (strided by H*W per channel, coalesced in w)
    float* o = out + (size_t)t * C_ * HW_ + hw;
    o[0 * HW_] = acc_lo.x;
    o[1 * HW_] = acc_lo.y;
    o[2 * HW_] = acc_lo.z;
    o[3 * HW_] = acc_lo.w;
    o[4 * HW_] = acc_hi.x;
    o[5 * HW_] = acc_hi.y;
    o[6 * HW_] = acc_hi.z;
    o[7 * HW_] = acc_hi.w;
}

// ---------------------------------------------------------------------------
extern "C" void kernel_launch(void* const* d_in, const int* in_sizes, int n_in,
                              void* d_out, int out_size) {
    const float* flows  = (const float*)d_in[0];   // [1,16,2,128,128]
    const float* images = (const float*)d_in[1];   // [1,16,8,128,128]
    float* out = (float*)d_out;                    // [1,16,8,128,128]

    (void)in_sizes; (void)n_in; (void)out_size;

    // 1) NCHW -> NHWC transpose of images into device scratch
    {
        int total = L_ * HW_;
        int threads = 256;
        int blocks = (total + threads - 1) / threads;
        transpose_nhwc_kernel<<<blocks, threads>>>(images);
    }

    // 2) fused flow suffix-sum + bilinear gather + triangular accumulation
    {
        dim3 grid(H_, L_);
        dim3 block(W_);
        pscan_sample_kernel<<<grid, block>>>(flows, out);
    }
}

// round 4
// speedup vs baseline: 1.7930x; 1.7930x over previous
#include <cuda_runtime.h>
#include <cuda_fp16.h>

// Problem: GridSamplePScan  B=1, L=16, C=8, H=128, W=128
// out[t,c,h,w] = sum_{k<=t} bilinear(images[k,c], base(h,w) + cum[t]-cum[k])
// x wrapped periodically (mod 2 normalized), zero-padding taps.
//
// R3: fp16 NHWC image scratch -> one LDG.128 per bilinear tap (was two fp32),
//     halving L1tex wavefront pressure (the measured 79.5% bottleneck).
//     (R2 resubmit with the compile error fixed.)

#define L_ 16
#define C_ 8
#define H_ 128
#define W_ 128
#define HW_ (H_ * W_)

// NHWC fp16 images scratch: [L, H, W, C] halves = 4 MB
__device__ __half g_imgT[L_ * H_ * W_ * C_];

// ---------------------------------------------------------------------------
// Kernel 1: transpose+quantize images [L,C,H,W] fp32 -> [L,H,W,C] fp16
// ---------------------------------------------------------------------------
__global__ __launch_bounds__(256) void transpose_nhwc_kernel(const float* __restrict__ images) {
    int idx = blockIdx.x * blockDim.x + threadIdx.x;  // over L*H*W
    if (idx >= L_ * HW_) return;
    int k = idx >> 14;           // / (H*W)
    int hw = idx & (HW_ - 1);

    const float* src = images + (size_t)k * C_ * HW_ + hw;
    float v0 = src[0 * HW_];
    float v1 = src[1 * HW_];
    float v2 = src[2 * HW_];
    float v3 = src[3 * HW_];
    float v4 = src[4 * HW_];
    float v5 = src[5 * HW_];
    float v6 = src[6 * HW_];
    float v7 = src[7 * HW_];

    __half2 h0 = __floats2half2_rn(v0, v1);
    __half2 h1 = __floats2half2_rn(v2, v3);
    __half2 h2 = __floats2half2_rn(v4, v5);
    __half2 h3 = __floats2half2_rn(v6, v7);

    uint4 pack;
    pack.x = *reinterpret_cast<unsigned int*>(&h0);
    pack.y = *reinterpret_cast<unsigned int*>(&h1);
    pack.z = *reinterpret_cast<unsigned int*>(&h2);
    pack.w = *reinterpret_cast<unsigned int*>(&h3);

    *reinterpret_cast<uint4*>(g_imgT + (size_t)idx * C_) = pack;
}

// ---------------------------------------------------------------------------
// Kernel 2: fused suffix-sum flow + bilinear gather + triangular accumulation
// One thread per (t, h, w); all 8 channels in registers. fp16 taps, fp32 math.
// ---------------------------------------------------------------------------
__device__ __forceinline__ void accum_tap(const uint4 p, const float wgt,
                                          float& a0, float& a1, float& a2, float& a3,
                                          float& a4, float& a5, float& a6, float& a7) {
    __half2 h0 = *reinterpret_cast<const __half2*>(&p.x);
    __half2 h1 = *reinterpret_cast<const __half2*>(&p.y);
    __half2 h2 = *reinterpret_cast<const __half2*>(&p.z);
    __half2 h3 = *reinterpret_cast<const __half2*>(&p.w);
    float2 f0 = __half22float2(h0);
    float2 f1 = __half22float2(h1);
    float2 f2 = __half22float2(h2);
    float2 f3 = __half22float2(h3);
    a0 = fmaf(wgt, f0.x, a0);
    a1 = fmaf(wgt, f0.y, a1);
    a2 = fmaf(wgt, f1.x, a2);
    a3 = fmaf(wgt, f1.y, a3);
    a4 = fmaf(wgt, f2.x, a4);
    a5 = fmaf(wgt, f2.y, a5);
    a6 = fmaf(wgt, f3.x, a6);
    a7 = fmaf(wgt, f3.y, a7);
}

__global__ __launch_bounds__(128) void pscan_sample_kernel(const float* __restrict__ flows,
                                                           float* __restrict__ out) {
    const int w = threadIdx.x;               // 0..127
    const int h = blockIdx.x;                // 0..127
    const int t = (L_ - 1) - blockIdx.y;     // long blocks (big t) first
    const int hw = h * W_ + w;

    // base grid (pixel centers, normalized, align_corners=False)
    const float bx = (2.0f * (float)w + 1.0f) * (1.0f / (float)W_) - 1.0f;
    const float by = (2.0f * (float)h + 1.0f) * (1.0f / (float)H_) - 1.0f;

    float a0 = 0.f, a1 = 0.f, a2 = 0.f, a3 = 0.f;
    float a4 = 0.f, a5 = 0.f, a6 = 0.f, a7 = 0.f;

    // rel(t,k) = cum[t]-cum[k] via suffix sum k = t..0
    float rx = 0.0f, ry = 0.0f;

    for (int k = t; k >= 0; --k) {
        float gx = bx + rx;
        float gy = by + ry;

        // periodic wrap in x (Python remainder semantics)
        float m = fmodf(gx + 1.0f, 2.0f);
        if (m < 0.0f) m += 2.0f;
        gx = m - 1.0f;

        float ix = (gx + 1.0f) * ((float)W_ * 0.5f) - 0.5f;
        float iy = (gy + 1.0f) * ((float)H_ * 0.5f) - 0.5f;

        float x0f = floorf(ix);
        float y0f = floorf(iy);
        float wx = ix - x0f;
        float wy = iy - y0f;

        int x0 = (int)x0f;
        int y0 = (int)y0f;
        int x1 = x0 + 1;
        int y1 = y0 + 1;

        float vx0 = (x0 >= 0 && x0 < W_) ? 1.0f : 0.0f;
        float vx1 = (x1 >= 0 && x1 < W_) ? 1.0f : 0.0f;
        float vy0 = (y0 >= 0 && y0 < H_) ? 1.0f : 0.0f;
        float vy1 = (y1 >= 0 && y1 < H_) ? 1.0f : 0.0f;

        int cx0 = min(max(x0, 0), W_ - 1);
        int cx1 = min(max(x1, 0), W_ - 1);
        int cy0 = min(max(y0, 0), H_ - 1);
        int cy1 = min(max(y1, 0), H_ - 1);

        float w00 = (1.0f - wx) * (1.0f - wy) * vx0 * vy0;
        float w10 = wx * (1.0f - wy) * vx1 * vy0;
        float w01 = (1.0f - wx) * wy * vx0 * vy1;
        float w11 = wx * wy * vx1 * vy1;

        const __half* imgk = g_imgT + (size_t)k * HW_ * C_;

        // issue all 4 tap loads up front (one LDG.128 each)
        uint4 p00 = *reinterpret_cast<const uint4*>(imgk + (size_t)(cy0 * W_ + cx0) * C_);
        uint4 p10 = *reinterpret_cast<const uint4*>(imgk + (size_t)(cy0 * W_ + cx1) * C_);
        uint4 p01 = *reinterpret_cast<const uint4*>(imgk + (size_t)(cy1 * W_ + cx0) * C_);
        uint4 p11 = *reinterpret_cast<const uint4*>(imgk + (size_t)(cy1 * W_ + cx1) * C_);

        // prefetch flow for next iter early
        float fx = 0.f, fy = 0.f;
        if (k > 0) {
            fx = __ldg(flows + (size_t)(k * 2 + 0) * HW_ + hw);
            fy = __ldg(flows + (size_t)(k * 2 + 1) * HW_ + hw);
        }

        accum_tap(p00, w00, a0, a1, a2, a3, a4, a5, a6, a7);
        accum_tap(p10, w10, a0, a1, a2, a3, a4, a5, a6, a7);
        accum_tap(p01, w01, a0, a1, a2, a3, a4, a5, a6, a7);
        accum_tap(p11, w11, a0, a1, a2, a3, a4, a5, a6, a7);

        rx += fx;
        ry += fy;
    }

    float* o = out + (size_t)t * C_ * HW_ + hw;
    o[0 * HW_] = a0;
    o[1 * HW_] = a1;
    o[2 * HW_] = a2;
    o[3 * HW_] = a3;
    o[4 * HW_] = a4;
    o[5 * HW_] = a5;
    o[6 * HW_] = a6;
    o[7 * HW_] = a7;
}

// ---------------------------------------------------------------------------
extern "C" void kernel_launch(void* const* d_in, const int* in_sizes, int n_in,
                              void* d_out, int out_size) {
    const float* flows  = (const float*)d_in[0];   // [1,16,2,128,128]
    const float* images = (const float*)d_in[1];   // [1,16,8,128,128]
    float* out = (float*)d_out;                    // [1,16,8,128,128]

    (void)in_sizes; (void)n_in; (void)out_size;

    {
        int total = L_ * HW_;
        int threads = 256;
        int blocks = (total + threads - 1) / threads;
        transpose_nhwc_kernel<<<blocks, threads>>>(images);
    }
    {
        dim3 grid(H_, L_);
        dim3 block(W_);
        pscan_sample_kernel<<<grid, block>>>(flows, out);
    }
}